// round 12
// baseline (speedup 1.0000x reference)
#include <cuda_runtime.h>
#include <math.h>
#include <stdint.h>

// ---------------- problem constants ----------------
#define T_TOK 2048
#define H_DIM 2048
#define I_DIM 1408
#define N1    (2*I_DIM)     // 2816
#define E_NUM 8
#define NPAIR (2*T_TOK)     // 4096

// ---------------- device scratch ----------------
__device__ int   g_cnt[E_NUM];
__device__ int   g_off[E_NUM];
__device__ int   g_cur[E_NUM];
__device__ int   g_tok_e[T_TOK][2];
__device__ float g_tok_w[T_TOK][2];
__device__ int   g_tok_row[T_TOK][2];
__device__ int   g_row_tok[NPAIR];
__device__ float g_gu[NPAIR][N1];      // gate_up (fp32)
__device__ float g_eo[NPAIR][H_DIM];   // expert_out (unweighted fp32)

// int8 2-limb quantized operands + per-row scales
__device__ int8_t g_xq_h[T_TOK][H_DIM];
__device__ int8_t g_xq_l[T_TOK][H_DIM];
__device__ float  g_xs[T_TOK];
__device__ int8_t g_w1q_h[E_NUM][N1][H_DIM];
__device__ int8_t g_w1q_l[E_NUM][N1][H_DIM];
__device__ float  g_w1s[E_NUM * N1];
__device__ int8_t g_w2q_h[E_NUM][H_DIM][I_DIM];
__device__ int8_t g_w2q_l[E_NUM][H_DIM][I_DIM];
__device__ float  g_w2s[E_NUM * H_DIM];
__device__ int8_t g_aq_h[NPAIR][I_DIM];
__device__ int8_t g_aq_l[NPAIR][I_DIM];
__device__ float  g_as[NPAIR];

// ---------------- helpers ----------------
__device__ __forceinline__ uint32_t smem_u32(const void* p) {
    uint32_t a;
    asm("{ .reg .u64 t; cvta.to.shared.u64 t, %1; cvt.u32.u64 %0, t; }" : "=r"(a) : "l"(p));
    return a;
}
#define CP16(dst, src, nbytes) \
    asm volatile("cp.async.ca.shared.global [%0], [%1], 16, %2;" \
                 :: "r"(dst), "l"(src), "r"(nbytes))
#define CP_COMMIT() asm volatile("cp.async.commit_group;" ::: "memory")
#define CP_WAIT(n)  asm volatile("cp.async.wait_group %0;" :: "n"(n) : "memory")

#define LDSM4(r0, r1, r2, r3, addr) \
    asm volatile("ldmatrix.sync.aligned.m8n8.x4.shared.b16 {%0,%1,%2,%3}, [%4];" \
                 : "=r"(r0), "=r"(r1), "=r"(r2), "=r"(r3) : "r"(addr))

// int8 m16n8k32 IMMA, s32 accum
#define MMA_S8(c0, c1, c2, c3, a0, a1, a2, a3, b0, b1) \
    asm volatile("mma.sync.aligned.m16n8k32.row.col.s32.s8.s8.s32 " \
        "{%0,%1,%2,%3}, {%4,%5,%6,%7}, {%8,%9}, {%0,%1,%2,%3};" \
        : "+r"(c0), "+r"(c1), "+r"(c2), "+r"(c3) \
        : "r"(a0), "r"(a1), "r"(a2), "r"(a3), "r"(b0), "r"(b1))

// smem: 4 tiles per buffer (Ahi, Alo, Bhi, Blo), 128 rows x 64 int8, stride 80B
#define SRB        80
#define TILE_B     (128 * SRB)   // 10240
#define OFF_ALO    TILE_B
#define OFF_BHI    (2 * TILE_B)
#define OFF_BLO    (3 * TILE_B)
#define BUF_B      (4 * TILE_B)  // 40960
#define SMEM_BYTES (2 * BUF_B)   // 81920

// ---------------- init / gating / scatter ----------------
__global__ void init_kernel() {
    int i = threadIdx.x;
    if (i < E_NUM) { g_cnt[i] = 0; g_cur[i] = 0; }
}

__global__ void gate_kernel(const float* __restrict__ x, const float* __restrict__ gw) {
    __shared__ float sx[H_DIM];
    __shared__ float logits[E_NUM];
    int t = blockIdx.x;
    const float* xr = x + (size_t)t * H_DIM;
    for (int i = threadIdx.x; i < H_DIM; i += blockDim.x) sx[i] = xr[i];
    __syncthreads();
    int w = threadIdx.x >> 5, lane = threadIdx.x & 31;
    const float* gr = gw + (size_t)w * H_DIM;
    float s = 0.f;
    for (int i = lane; i < H_DIM; i += 32) s += sx[i] * gr[i];
    #pragma unroll
    for (int o = 16; o; o >>= 1) s += __shfl_xor_sync(0xffffffffu, s, o);
    if (lane == 0) logits[w] = s;
    __syncthreads();
    if (threadIdx.x == 0) {
        int i0 = 0;
        #pragma unroll
        for (int e = 1; e < E_NUM; e++) if (logits[e] > logits[i0]) i0 = e;
        int i1 = (i0 == 0) ? 1 : 0;
        #pragma unroll
        for (int e = 0; e < E_NUM; e++) {
            if (e == i0 || e == i1) continue;
            if (logits[e] > logits[i1]) i1 = e;
        }
        float ex = expf(logits[i1] - logits[i0]);
        float w0 = 1.f / (1.f + ex);
        float w1 = ex / (1.f + ex);
        g_tok_e[t][0] = i0; g_tok_e[t][1] = i1;
        g_tok_w[t][0] = w0; g_tok_w[t][1] = w1;
        atomicAdd(&g_cnt[i0], 1); atomicAdd(&g_cnt[i1], 1);
    }
}

__global__ void offs_kernel() {
    if (threadIdx.x == 0) {
        int o = 0;
        #pragma unroll
        for (int e = 0; e < E_NUM; e++) { g_off[e] = o; o += g_cnt[e]; }
    }
}

__global__ void scatter_kernel() {
    int t = blockIdx.x * blockDim.x + threadIdx.x;
    if (t >= T_TOK) return;
    #pragma unroll
    for (int k = 0; k < 2; k++) {
        int e = g_tok_e[t][k];
        int p = atomicAdd(&g_cur[e], 1);
        int r = g_off[e] + p;
        g_row_tok[r] = t;
        g_tok_row[t][k] = r;
    }
}

// ---------------- per-row int8 2-limb quantization ----------------
// x = s/127*(hi + lo/254); DST: 0 = x, 1 = w1, 2 = w2 (device-resolved)
template<int DST, int K>
__global__ __launch_bounds__(256)
void quant_kernel(const float* __restrict__ src) {
    const int row = blockIdx.x;
    const float* r = src + (size_t)row * K;
    __shared__ float red[8];
    __shared__ float s_bcast;
    int tid = threadIdx.x, lane = tid & 31, wid = tid >> 5;

    float m = 0.f;
    for (int i = tid; i < K; i += 256) m = fmaxf(m, fabsf(r[i]));
    #pragma unroll
    for (int o = 16; o; o >>= 1) m = fmaxf(m, __shfl_xor_sync(0xffffffffu, m, o));
    if (lane == 0) red[wid] = m;
    __syncthreads();
    if (tid == 0) {
        float s = red[0];
        #pragma unroll
        for (int i = 1; i < 8; i++) s = fmaxf(s, red[i]);
        s = fmaxf(s, 1e-20f);
        s_bcast = s;
        if (DST == 0)      g_xs[row]  = s;
        else if (DST == 1) g_w1s[row] = s;
        else               g_w2s[row] = s;
    }
    __syncthreads();
    const float inv = 127.f / s_bcast;

    int8_t* hi; int8_t* lo;
    if (DST == 0)      { hi = &g_xq_h[0][0];     lo = &g_xq_l[0][0]; }
    else if (DST == 1) { hi = &g_w1q_h[0][0][0]; lo = &g_w1q_l[0][0][0]; }
    else               { hi = &g_w2q_h[0][0][0]; lo = &g_w2q_l[0][0][0]; }
    hi += (size_t)row * K; lo += (size_t)row * K;

    for (int i = tid; i < K; i += 256) {
        float v = r[i] * inv;
        int h = __float2int_rn(v);
        int l = __float2int_rn((v - (float)h) * 254.f);
        hi[i] = (int8_t)h;
        lo[i] = (int8_t)l;
    }
}

// ---------------- int8 2-limb IMMA grouped GEMM ----------------
// C[row, n] = sA[row]*sB[n]/16129 * (hh + cross/254)
// 128x128x64 tiles; 8 warps (2m x 4n), warp tile 64x32, m16n8k32 s8 IMMA.
template<int NK, int KSTRIDE, int NROWS, int OUTSTRIDE, bool GATHER>
__global__ __launch_bounds__(256, 1)
void moe_gemm() {
    extern __shared__ char smc[];
    const int e    = blockIdx.z;
    const int cnt  = g_cnt[e];
    const int base = g_off[e];
    const int m0   = blockIdx.y * 128;
    if (m0 >= cnt) return;
    const int n0 = blockIdx.x * 128;

    // device-side pointer resolution
    const int8_t* aHi; const int8_t* aLo; const float* aS;
    const int8_t* wHi; const int8_t* wLo; const float* wS;
    float* Out;
    if (GATHER) {
        aHi = &g_xq_h[0][0];      aLo = &g_xq_l[0][0];      aS = g_xs;
        wHi = &g_w1q_h[0][0][0];  wLo = &g_w1q_l[0][0][0];  wS = g_w1s;
        Out = &g_gu[0][0];
    } else {
        aHi = &g_aq_h[0][0];      aLo = &g_aq_l[0][0];      aS = g_as;
        wHi = &g_w2q_h[0][0][0];  wLo = &g_w2q_l[0][0][0];  wS = g_w2s;
        Out = &g_eo[0][0];
    }

    const uint32_t smb = smem_u32(smc);
    const int tid  = threadIdx.x;
    const int lane = tid & 31;
    const int wid  = tid >> 5;
    const int wm   = wid >> 2;
    const int wn   = wid & 3;

    const int srow = tid >> 1;            // 0..127
    const int half = tid & 1;
    const bool a_ok = (m0 + srow) < cnt;
    int arow_idx;
    if (GATHER) arow_idx = a_ok ? g_row_tok[base + m0 + srow] : 0;
    else        arow_idx = a_ok ? (base + m0 + srow) : 0;
    const int8_t* aHiRow = aHi + (size_t)arow_idx * KSTRIDE;
    const int8_t* aLoRow = aLo + (size_t)arow_idx * KSTRIDE;
    const int8_t* bHiRow = wHi + (size_t)e * NROWS * KSTRIDE + (size_t)(n0 + srow) * KSTRIDE;
    const int8_t* bLoRow = wLo + (size_t)e * NROWS * KSTRIDE + (size_t)(n0 + srow) * KSTRIDE;
    const int a_n = a_ok ? 16 : 0;

    auto stage = [&](int kt, int b) {
        uint32_t s0 = smb + (uint32_t)(b * BUF_B);
        #pragma unroll
        for (int j = 0; j < 2; j++) {
            int c = half * 2 + j;                      // 16B chunk 0..3
            uint32_t doff = (uint32_t)(srow * SRB + c * 16);
            int goff = kt * 64 + c * 16;               // int8 elements = bytes
            CP16(s0 + doff,           aHiRow + goff, a_n);
            CP16(s0 + OFF_ALO + doff, aLoRow + goff, a_n);
            CP16(s0 + OFF_BHI + doff, bHiRow + goff, 16);
            CP16(s0 + OFF_BLO + doff, bLoRow + goff, 16);
        }
        CP_COMMIT();
    };

    stage(0, 0);
    stage(1, 1);

    int acc_h[4][4][4];   // hi*hi
    int acc_c[4][4][4];   // hi*lo + lo*hi (scale 1/254)
    #pragma unroll
    for (int i = 0; i < 4; i++)
        #pragma unroll
        for (int j = 0; j < 4; j++)
            #pragma unroll
            for (int q = 0; q < 4; q++) { acc_h[i][j][q] = 0; acc_c[i][j][q] = 0; }

    const int quad = lane >> 3, lr = lane & 7;
    const uint32_t a_base = (uint32_t)((wm * 64 + (quad & 1) * 8 + lr) * SRB + (quad >> 1) * 16);
    const uint32_t b_base = (uint32_t)((wn * 32 + (quad >> 1) * 8 + lr) * SRB + (quad & 1) * 16);

    for (int kt = 0; kt < NK; kt++) {
        if (kt == NK - 1) CP_WAIT(0); else CP_WAIT(1);
        __syncthreads();
        const uint32_t bufa = smb + (uint32_t)((kt & 1) * BUF_B);
        #pragma unroll
        for (int ks = 0; ks < 2; ks++) {
            const uint32_t ko = (uint32_t)(ks * 32);   // k32 int8 step = 32B
            uint32_t ah[4][4], al[4][4];
            #pragma unroll
            for (int mf = 0; mf < 4; mf++) {
                uint32_t ad = bufa + a_base + (uint32_t)(mf * 16 * SRB) + ko;
                LDSM4(ah[mf][0], ah[mf][1], ah[mf][2], ah[mf][3], ad);
                LDSM4(al[mf][0], al[mf][1], al[mf][2], al[mf][3], ad + OFF_ALO);
            }
            uint32_t bh[4][2], bl[4][2];
            #pragma unroll
            for (int p = 0; p < 2; p++) {
                uint32_t bd = bufa + OFF_BHI + b_base + (uint32_t)(p * 16 * SRB) + ko;
                uint32_t t0, t1, t2, t3;
                LDSM4(t0, t1, t2, t3, bd);
                bh[2*p][0] = t0; bh[2*p][1] = t1; bh[2*p+1][0] = t2; bh[2*p+1][1] = t3;
                LDSM4(t0, t1, t2, t3, bd + TILE_B);
                bl[2*p][0] = t0; bl[2*p][1] = t1; bl[2*p+1][0] = t2; bl[2*p+1][1] = t3;
            }
            #pragma unroll
            for (int mf = 0; mf < 4; mf++)
                #pragma unroll
                for (int nf = 0; nf < 4; nf++) {
                    MMA_S8(acc_h[mf][nf][0], acc_h[mf][nf][1], acc_h[mf][nf][2], acc_h[mf][nf][3],
                           ah[mf][0], ah[mf][1], ah[mf][2], ah[mf][3],
                           bh[nf][0], bh[nf][1]);
                    MMA_S8(acc_c[mf][nf][0], acc_c[mf][nf][1], acc_c[mf][nf][2], acc_c[mf][nf][3],
                           ah[mf][0], ah[mf][1], ah[mf][2], ah[mf][3],
                           bl[nf][0], bl[nf][1]);
                    MMA_S8(acc_c[mf][nf][0], acc_c[mf][nf][1], acc_c[mf][nf][2], acc_c[mf][nf][3],
                           al[mf][0], al[mf][1], al[mf][2], al[mf][3],
                           bh[nf][0], bh[nf][1]);
                }
        }
        __syncthreads();
        if (kt + 2 < NK) stage(kt + 2, kt & 1);
    }

    // epilogue with per-row scales
    const int qrow = lane >> 2;
    const int qk   = lane & 3;
    const float* sB = wS + (size_t)e * NROWS;
    const float inv2 = 1.f / 16129.f;      // 1/127^2
    const float invc = 1.f / 254.f;
    #pragma unroll
    for (int mf = 0; mf < 4; mf++) {
        int ml = wm * 64 + mf * 16 + qrow;
        int m1 = m0 + ml;
        int m2 = m1 + 8;
        float sa1 = 0.f, sa2 = 0.f;
        if (m1 < cnt) sa1 = (GATHER ? aS[g_row_tok[base + m1]] : aS[base + m1]) * inv2;
        if (m2 < cnt) sa2 = (GATHER ? aS[g_row_tok[base + m2]] : aS[base + m2]) * inv2;
        #pragma unroll
        for (int nf = 0; nf < 4; nf++) {
            int col = n0 + wn * 32 + nf * 8 + qk * 2;
            float sb0 = sB[col], sb1 = sB[col + 1];
            if (m1 < cnt) {
                float v0 = sa1 * sb0 * ((float)acc_h[mf][nf][0] + (float)acc_c[mf][nf][0] * invc);
                float v1 = sa1 * sb1 * ((float)acc_h[mf][nf][1] + (float)acc_c[mf][nf][1] * invc);
                *(float2*)(Out + (size_t)(base + m1) * OUTSTRIDE + col) = make_float2(v0, v1);
            }
            if (m2 < cnt) {
                float v0 = sa2 * sb0 * ((float)acc_h[mf][nf][2] + (float)acc_c[mf][nf][2] * invc);
                float v1 = sa2 * sb1 * ((float)acc_h[mf][nf][3] + (float)acc_c[mf][nf][3] * invc);
                *(float2*)(Out + (size_t)(base + m2) * OUTSTRIDE + col) = make_float2(v0, v1);
            }
        }
    }
}

// ---------------- activation: act = silu(g)*u, fused per-row quantization ---
__global__ __launch_bounds__(256)
void act_kernel() {
    const int r = blockIdx.x;  // 0..NPAIR-1
    __shared__ float sact[I_DIM];
    __shared__ float red[8];
    __shared__ float s_bcast;
    int tid = threadIdx.x, lane = tid & 31, wid = tid >> 5;

    float m = 0.f;
    for (int i = tid; i < I_DIM; i += 256) {
        float g = g_gu[r][i];
        float u = g_gu[r][I_DIM + i];
        float a = g / (1.f + expf(-g)) * u;
        sact[i] = a;
        m = fmaxf(m, fabsf(a));
    }
    #pragma unroll
    for (int o = 16; o; o >>= 1) m = fmaxf(m, __shfl_xor_sync(0xffffffffu, m, o));
    if (lane == 0) red[wid] = m;
    __syncthreads();
    if (tid == 0) {
        float s = red[0];
        #pragma unroll
        for (int i = 1; i < 8; i++) s = fmaxf(s, red[i]);
        s = fmaxf(s, 1e-20f);
        s_bcast = s;
        g_as[r] = s;
    }
    __syncthreads();
    const float inv = 127.f / s_bcast;
    for (int i = tid; i < I_DIM; i += 256) {
        float v = sact[i] * inv;
        int h = __float2int_rn(v);
        int l = __float2int_rn((v - (float)h) * 254.f);
        g_aq_h[r][i] = (int8_t)h;
        g_aq_l[r][i] = (int8_t)l;
    }
}

// ---------------- combine: out[t] = w0*eo[r0] + w1*eo[r1] ----------------
__global__ void combine_kernel(float* __restrict__ out) {
    int idx = blockIdx.x * blockDim.x + threadIdx.x;
    const int per_tok = H_DIM / 4;
    if (idx >= T_TOK * per_tok) return;
    int t  = idx / per_tok;
    int c4 = (idx % per_tok) * 4;
    int r0 = g_tok_row[t][0], r1 = g_tok_row[t][1];
    float w0 = g_tok_w[t][0], w1 = g_tok_w[t][1];
    float4 a = *(const float4*)&g_eo[r0][c4];
    float4 b = *(const float4*)&g_eo[r1][c4];
    float4 o;
    o.x = w0 * a.x + w1 * b.x;
    o.y = w0 * a.y + w1 * b.y;
    o.z = w0 * a.z + w1 * b.z;
    o.w = w0 * a.w + w1 * b.w;
    *(float4*)(out + (size_t)t * H_DIM + c4) = o;
}

// ---------------- launch ----------------
extern "C" void kernel_launch(void* const* d_in, const int* in_sizes, int n_in,
                              void* d_out, int out_size) {
    const float* x  = (const float*)d_in[0];
    const float* gw = (const float*)d_in[1];
    const float* w1 = (const float*)d_in[2];
    const float* w2 = (const float*)d_in[3];
    float* out = (float*)d_out;

    cudaFuncSetAttribute(moe_gemm<H_DIM/64, H_DIM, N1, N1, true>,
                         cudaFuncAttributeMaxDynamicSharedMemorySize, SMEM_BYTES);
    cudaFuncSetAttribute(moe_gemm<I_DIM/64, I_DIM, H_DIM, H_DIM, false>,
                         cudaFuncAttributeMaxDynamicSharedMemorySize, SMEM_BYTES);

    init_kernel<<<1, 32>>>();
    gate_kernel<<<T_TOK, 256>>>(x, gw);
    offs_kernel<<<1, 32>>>();
    scatter_kernel<<<(T_TOK + 255) / 256, 256>>>();

    // int8 2-limb quantization (destinations resolved device-side)
    quant_kernel<0, H_DIM><<<T_TOK, 256>>>(x);
    quant_kernel<1, H_DIM><<<E_NUM * N1, 256>>>(w1);
    quant_kernel<2, I_DIM><<<E_NUM * H_DIM, 256>>>(w2);

    dim3 grid1(N1 / 128, T_TOK / 128, E_NUM);    // 22 x 16 x 8
    moe_gemm<H_DIM/64, H_DIM, N1, N1, true><<<grid1, 256, SMEM_BYTES>>>();

    act_kernel<<<NPAIR, 256>>>();

    dim3 grid2(H_DIM / 128, T_TOK / 128, E_NUM); // 16 x 16 x 8
    moe_gemm<I_DIM/64, I_DIM, H_DIM, H_DIM, false><<<grid2, 256, SMEM_BYTES>>>();

    combine_kernel<<<(T_TOK * (H_DIM / 4) + 255) / 256, 256>>>(out);
}

// round 13
// speedup vs baseline: 2.3237x; 2.3237x over previous
#include <cuda_runtime.h>
#include <cuda_bf16.h>
#include <math.h>
#include <stdint.h>

// ---------------- problem constants ----------------
#define T_TOK 2048
#define H_DIM 2048
#define I_DIM 1408
#define N1    (2*I_DIM)     // 2816
#define E_NUM 8
#define NPAIR (2*T_TOK)     // 4096

// ---------------- device scratch ----------------
__device__ int   g_cnt[E_NUM];
__device__ int   g_off[E_NUM];
__device__ int   g_cur[E_NUM];
__device__ int   g_tok_e[T_TOK][2];
__device__ float g_tok_w[T_TOK][2];
__device__ int   g_tok_row[T_TOK][2];
__device__ int   g_row_tok[NPAIR];
__device__ float g_gu[NPAIR][N1];      // gate_up (fp32)
__device__ float g_eo[NPAIR][H_DIM];   // expert_out (unweighted fp32)

// pre-split bf16 hi/lo operands
__device__ __nv_bfloat16 g_x_hi[T_TOK][H_DIM];
__device__ __nv_bfloat16 g_x_lo[T_TOK][H_DIM];
__device__ __nv_bfloat16 g_w1_hi[E_NUM][N1][H_DIM];
__device__ __nv_bfloat16 g_w1_lo[E_NUM][N1][H_DIM];
__device__ __nv_bfloat16 g_w2_hi[E_NUM][H_DIM][I_DIM];
__device__ __nv_bfloat16 g_w2_lo[E_NUM][H_DIM][I_DIM];
__device__ __nv_bfloat16 g_act_hi[NPAIR][I_DIM];
__device__ __nv_bfloat16 g_act_lo[NPAIR][I_DIM];

// ---------------- helpers ----------------
__device__ __forceinline__ uint32_t smem_u32(const void* p) {
    uint32_t a;
    asm("{ .reg .u64 t; cvta.to.shared.u64 t, %1; cvt.u32.u64 %0, t; }" : "=r"(a) : "l"(p));
    return a;
}
#define CP16(dst, src, nbytes) \
    asm volatile("cp.async.ca.shared.global [%0], [%1], 16, %2;" \
                 :: "r"(dst), "l"(src), "r"(nbytes))
#define CP_COMMIT() asm volatile("cp.async.commit_group;" ::: "memory")
#define CP_WAIT(n)  asm volatile("cp.async.wait_group %0;" :: "n"(n) : "memory")

#define LDSM4(r0, r1, r2, r3, addr) \
    asm volatile("ldmatrix.sync.aligned.m8n8.x4.shared.b16 {%0,%1,%2,%3}, [%4];" \
                 : "=r"(r0), "=r"(r1), "=r"(r2), "=r"(r3) : "r"(addr))

__device__ __forceinline__ void mma_bf16(float& c0, float& c1, float& c2, float& c3,
                                         uint32_t a0, uint32_t a1, uint32_t a2, uint32_t a3,
                                         uint32_t b0, uint32_t b1) {
    asm volatile(
        "mma.sync.aligned.m16n8k16.row.col.f32.bf16.bf16.f32 "
        "{%0,%1,%2,%3}, {%4,%5,%6,%7}, {%8,%9}, {%0,%1,%2,%3};"
        : "+f"(c0), "+f"(c1), "+f"(c2), "+f"(c3)
        : "r"(a0), "r"(a1), "r"(a2), "r"(a3), "r"(b0), "r"(b1));
}

// split fp32 pair (x, y) -> packed bf16x2 hi (low half = x) + bf16x2 lo residual
__device__ __forceinline__ void split2(float x, float y, uint32_t& hi, uint32_t& lo) {
    uint32_t h;
    asm("cvt.rn.bf16x2.f32 %0, %1, %2;" : "=r"(h) : "f"(y), "f"(x));
    float hx = __uint_as_float(h << 16);
    float hy = __uint_as_float(h & 0xFFFF0000u);
    float lx = x - hx, ly = y - hy;
    asm("cvt.rn.bf16x2.f32 %0, %1, %2;" : "=r"(lo) : "f"(ly), "f"(lx));
    hi = h;
}

// smem: CTA tile 128x256, k32. Tiles: Ahi(128r) Alo(128r) Bhi(256r) Blo(256r),
// each row = 32 bf16 = 64B data, stride 80B (conflict-free ldmatrix).
#define SRB        80
#define A_ROWS     128
#define B_ROWS     256
#define OFF_ALO    (A_ROWS * SRB)              // 10240
#define OFF_BHI    (2 * A_ROWS * SRB)          // 20480
#define OFF_BDELTA (B_ROWS * SRB)              // 20480 (Blo = Bhi + this)
#define BUF_B      (OFF_BHI + 2 * B_ROWS * SRB) // 61440
#define SMEM_BYTES (2 * BUF_B)                  // 122880

// ---------------- init / gating / scatter ----------------
__global__ void init_kernel() {
    int i = threadIdx.x;
    if (i < E_NUM) { g_cnt[i] = 0; g_cur[i] = 0; }
}

__global__ void gate_kernel(const float* __restrict__ x, const float* __restrict__ gw) {
    __shared__ float sx[H_DIM];
    __shared__ float logits[E_NUM];
    int t = blockIdx.x;
    const float* xr = x + (size_t)t * H_DIM;
    for (int i = threadIdx.x; i < H_DIM; i += blockDim.x) sx[i] = xr[i];
    __syncthreads();
    int w = threadIdx.x >> 5, lane = threadIdx.x & 31;
    const float* gr = gw + (size_t)w * H_DIM;
    float s = 0.f;
    for (int i = lane; i < H_DIM; i += 32) s += sx[i] * gr[i];
    #pragma unroll
    for (int o = 16; o; o >>= 1) s += __shfl_xor_sync(0xffffffffu, s, o);
    if (lane == 0) logits[w] = s;
    __syncthreads();
    if (threadIdx.x == 0) {
        int i0 = 0;
        #pragma unroll
        for (int e = 1; e < E_NUM; e++) if (logits[e] > logits[i0]) i0 = e;
        int i1 = (i0 == 0) ? 1 : 0;
        #pragma unroll
        for (int e = 0; e < E_NUM; e++) {
            if (e == i0 || e == i1) continue;
            if (logits[e] > logits[i1]) i1 = e;
        }
        float ex = expf(logits[i1] - logits[i0]);
        float w0 = 1.f / (1.f + ex);
        float w1 = ex / (1.f + ex);
        g_tok_e[t][0] = i0; g_tok_e[t][1] = i1;
        g_tok_w[t][0] = w0; g_tok_w[t][1] = w1;
        atomicAdd(&g_cnt[i0], 1); atomicAdd(&g_cnt[i1], 1);
    }
}

__global__ void offs_kernel() {
    if (threadIdx.x == 0) {
        int o = 0;
        #pragma unroll
        for (int e = 0; e < E_NUM; e++) { g_off[e] = o; o += g_cnt[e]; }
    }
}

__global__ void scatter_kernel() {
    int t = blockIdx.x * blockDim.x + threadIdx.x;
    if (t >= T_TOK) return;
    #pragma unroll
    for (int k = 0; k < 2; k++) {
        int e = g_tok_e[t][k];
        int p = atomicAdd(&g_cur[e], 1);
        int r = g_off[e] + p;
        g_row_tok[r] = t;
        g_tok_row[t][k] = r;
    }
}

// ---------------- pre-split fp32 -> bf16 hi/lo ----------------
template<int DST>
__global__ void split_kernel(const float* __restrict__ in, int n4) {
    int idx = blockIdx.x * blockDim.x + threadIdx.x;
    if (idx >= n4) return;
    __nv_bfloat16* hi;
    __nv_bfloat16* lo;
    if (DST == 0)      { hi = &g_x_hi[0][0];     lo = &g_x_lo[0][0]; }
    else if (DST == 1) { hi = &g_w1_hi[0][0][0]; lo = &g_w1_lo[0][0][0]; }
    else               { hi = &g_w2_hi[0][0][0]; lo = &g_w2_lo[0][0][0]; }
    float4 v = ((const float4*)in)[idx];
    uint32_t h01, l01, h23, l23;
    split2(v.x, v.y, h01, l01);
    split2(v.z, v.w, h23, l23);
    ((uint2*)hi)[idx] = make_uint2(h01, h23);
    ((uint2*)lo)[idx] = make_uint2(l01, l23);
}

// ---------------- bf16x3 mma.sync grouped GEMM ----------------
// C[row, n] = sum_k A[row, k] * W_e[n, k]
// CTA tile 128x256xk32; 8 warps (2m x 4n), warp tile 64x64, m16n8k16 bf16.
template<int NK, int KSTRIDE, int NROWS, int OUTSTRIDE, bool GATHER>
__global__ __launch_bounds__(256, 1)
void moe_gemm() {
    extern __shared__ char smc[];
    const int e    = blockIdx.z;
    const int cnt  = g_cnt[e];
    const int base = g_off[e];
    const int m0   = blockIdx.y * 128;
    if (m0 >= cnt) return;
    const int n0 = blockIdx.x * 256;

    const __nv_bfloat16* aHi;
    const __nv_bfloat16* aLo;
    const __nv_bfloat16* wHi;
    const __nv_bfloat16* wLo;
    float* Out;
    if (GATHER) {
        aHi = &g_x_hi[0][0];      aLo = &g_x_lo[0][0];
        wHi = &g_w1_hi[0][0][0];  wLo = &g_w1_lo[0][0][0];
        Out = &g_gu[0][0];
    } else {
        aHi = &g_act_hi[0][0];    aLo = &g_act_lo[0][0];
        wHi = &g_w2_hi[0][0][0];  wLo = &g_w2_lo[0][0][0];
        Out = &g_eo[0][0];
    }

    const uint32_t smb = smem_u32(smc);
    const int tid  = threadIdx.x;
    const int lane = tid & 31;
    const int wid  = tid >> 5;
    const int wm   = wid >> 2;            // m offset wm*64
    const int wn   = wid & 3;             // n offset wn*64

    // staging: thread -> A row srow (2 chunks) + B rows srow, srow+128 (2 chunks each)
    const int srow = tid >> 1;            // 0..127
    const int half = tid & 1;             // chunk pair {0,1} or {2,3}
    const bool a_ok = (m0 + srow) < cnt;
    int arow_idx;
    if (GATHER) arow_idx = a_ok ? g_row_tok[base + m0 + srow] : 0;
    else        arow_idx = a_ok ? (base + m0 + srow) : 0;
    const __nv_bfloat16* aHiRow = aHi + (size_t)arow_idx * KSTRIDE;
    const __nv_bfloat16* aLoRow = aLo + (size_t)arow_idx * KSTRIDE;
    const size_t wBase = (size_t)e * NROWS * KSTRIDE;
    const __nv_bfloat16* bHiRow0 = wHi + wBase + (size_t)(n0 + srow) * KSTRIDE;
    const __nv_bfloat16* bHiRow1 = bHiRow0 + (size_t)128 * KSTRIDE;
    const __nv_bfloat16* bLoRow0 = wLo + wBase + (size_t)(n0 + srow) * KSTRIDE;
    const __nv_bfloat16* bLoRow1 = bLoRow0 + (size_t)128 * KSTRIDE;
    const int a_n = a_ok ? 16 : 0;

    auto stage = [&](int kt, int b) {
        uint32_t s0 = smb + (uint32_t)(b * BUF_B);
        #pragma unroll
        for (int j = 0; j < 2; j++) {
            int c = half * 2 + j;                      // 16B chunk 0..3
            uint32_t doff = (uint32_t)(srow * SRB + c * 16);
            int goff = kt * 32 + c * 8;                // bf16 elements
            CP16(s0 + doff,            aHiRow  + goff, a_n);
            CP16(s0 + OFF_ALO + doff,  aLoRow  + goff, a_n);
            uint32_t bo = s0 + OFF_BHI + doff;
            CP16(bo,                        bHiRow0 + goff, 16);
            CP16(bo + 128 * SRB,            bHiRow1 + goff, 16);
            CP16(bo + OFF_BDELTA,           bLoRow0 + goff, 16);
            CP16(bo + OFF_BDELTA + 128*SRB, bLoRow1 + goff, 16);
        }
        CP_COMMIT();
    };

    stage(0, 0);
    stage(1, 1);

    float acc[4][8][4];
    #pragma unroll
    for (int i = 0; i < 4; i++)
        #pragma unroll
        for (int j = 0; j < 8; j++)
            #pragma unroll
            for (int q = 0; q < 4; q++) acc[i][j][q] = 0.f;

    const int quad = lane >> 3, lr = lane & 7;
    const uint32_t a_base = (uint32_t)((wm * 64 + (quad & 1) * 8 + lr) * SRB + (quad >> 1) * 16);
    const uint32_t b_base = (uint32_t)((wn * 64 + (quad >> 1) * 8 + lr) * SRB + (quad & 1) * 16);

    for (int kt = 0; kt < NK; kt++) {
        if (kt == NK - 1) CP_WAIT(0); else CP_WAIT(1);
        __syncthreads();
        const uint32_t bufa = smb + (uint32_t)((kt & 1) * BUF_B);
        #pragma unroll
        for (int ks = 0; ks < 2; ks++) {
            const uint32_t ko = (uint32_t)(ks * 32);   // k16 step = 32B
            uint32_t ah[4][4], al[4][4];
            #pragma unroll
            for (int mf = 0; mf < 4; mf++) {
                uint32_t ad = bufa + a_base + (uint32_t)(mf * 16 * SRB) + ko;
                LDSM4(ah[mf][0], ah[mf][1], ah[mf][2], ah[mf][3], ad);
                LDSM4(al[mf][0], al[mf][1], al[mf][2], al[mf][3], ad + OFF_ALO);
            }
            #pragma unroll
            for (int p = 0; p < 4; p++) {              // 16 B-rows per p -> nf pair
                uint32_t bd = bufa + OFF_BHI + b_base + (uint32_t)(p * 16 * SRB) + ko;
                uint32_t bh[2][2], bl[2][2];
                uint32_t t0, t1, t2, t3;
                LDSM4(t0, t1, t2, t3, bd);
                bh[0][0] = t0; bh[0][1] = t1; bh[1][0] = t2; bh[1][1] = t3;
                LDSM4(t0, t1, t2, t3, bd + OFF_BDELTA);
                bl[0][0] = t0; bl[0][1] = t1; bl[1][0] = t2; bl[1][1] = t3;
                #pragma unroll
                for (int mf = 0; mf < 4; mf++)
                    #pragma unroll
                    for (int q = 0; q < 2; q++) {
                        const int nf = p * 2 + q;
                        mma_bf16(acc[mf][nf][0], acc[mf][nf][1], acc[mf][nf][2], acc[mf][nf][3],
                                 ah[mf][0], ah[mf][1], ah[mf][2], ah[mf][3],
                                 bh[q][0], bh[q][1]);
                        mma_bf16(acc[mf][nf][0], acc[mf][nf][1], acc[mf][nf][2], acc[mf][nf][3],
                                 ah[mf][0], ah[mf][1], ah[mf][2], ah[mf][3],
                                 bl[q][0], bl[q][1]);
                        mma_bf16(acc[mf][nf][0], acc[mf][nf][1], acc[mf][nf][2], acc[mf][nf][3],
                                 al[mf][0], al[mf][1], al[mf][2], al[mf][3],
                                 bh[q][0], bh[q][1]);
                    }
            }
        }
        __syncthreads();
        if (kt + 2 < NK) stage(kt + 2, kt & 1);
    }

    const int qrow = lane >> 2;
    const int qk   = lane & 3;
    #pragma unroll
    for (int mf = 0; mf < 4; mf++) {
        int ml = wm * 64 + mf * 16 + qrow;
        int m1 = m0 + ml;
        int m2 = m1 + 8;
        #pragma unroll
        for (int nf = 0; nf < 8; nf++) {
            int col = n0 + wn * 64 + nf * 8 + qk * 2;
            if (m1 < cnt) {
                float2 v = make_float2(acc[mf][nf][0], acc[mf][nf][1]);
                *(float2*)(Out + (size_t)(base + m1) * OUTSTRIDE + col) = v;
            }
            if (m2 < cnt) {
                float2 v = make_float2(acc[mf][nf][2], acc[mf][nf][3]);
                *(float2*)(Out + (size_t)(base + m2) * OUTSTRIDE + col) = v;
            }
        }
    }
}

// ---------------- activation: act = silu(g) * u, split to bf16 hi/lo --------
__global__ void act_kernel() {
    int idx = blockIdx.x * blockDim.x + threadIdx.x;
    const int total = NPAIR * (I_DIM / 4);
    if (idx >= total) return;
    int r  = idx / (I_DIM / 4);
    int c4 = (idx % (I_DIM / 4)) * 4;
    float4 g = *(const float4*)&g_gu[r][c4];
    float4 u = *(const float4*)&g_gu[r][I_DIM + c4];
    float4 o;
    o.x = g.x / (1.f + expf(-g.x)) * u.x;
    o.y = g.y / (1.f + expf(-g.y)) * u.y;
    o.z = g.z / (1.f + expf(-g.z)) * u.z;
    o.w = g.w / (1.f + expf(-g.w)) * u.w;
    uint32_t h01, l01, h23, l23;
    split2(o.x, o.y, h01, l01);
    split2(o.z, o.w, h23, l23);
    *(uint2*)&g_act_hi[r][c4] = make_uint2(h01, h23);
    *(uint2*)&g_act_lo[r][c4] = make_uint2(l01, l23);
}

// ---------------- combine: out[t] = w0*eo[r0] + w1*eo[r1] ----------------
__global__ void combine_kernel(float* __restrict__ out) {
    int idx = blockIdx.x * blockDim.x + threadIdx.x;
    const int per_tok = H_DIM / 4;
    if (idx >= T_TOK * per_tok) return;
    int t  = idx / per_tok;
    int c4 = (idx % per_tok) * 4;
    int r0 = g_tok_row[t][0], r1 = g_tok_row[t][1];
    float w0 = g_tok_w[t][0], w1 = g_tok_w[t][1];
    float4 a = *(const float4*)&g_eo[r0][c4];
    float4 b = *(const float4*)&g_eo[r1][c4];
    float4 o;
    o.x = w0 * a.x + w1 * b.x;
    o.y = w0 * a.y + w1 * b.y;
    o.z = w0 * a.z + w1 * b.z;
    o.w = w0 * a.w + w1 * b.w;
    *(float4*)(out + (size_t)t * H_DIM + c4) = o;
}

// ---------------- launch ----------------
extern "C" void kernel_launch(void* const* d_in, const int* in_sizes, int n_in,
                              void* d_out, int out_size) {
    const float* x  = (const float*)d_in[0];
    const float* gw = (const float*)d_in[1];
    const float* w1 = (const float*)d_in[2];
    const float* w2 = (const float*)d_in[3];
    float* out = (float*)d_out;

    cudaFuncSetAttribute(moe_gemm<H_DIM/32, H_DIM, N1, N1, true>,
                         cudaFuncAttributeMaxDynamicSharedMemorySize, SMEM_BYTES);
    cudaFuncSetAttribute(moe_gemm<I_DIM/32, I_DIM, H_DIM, H_DIM, false>,
                         cudaFuncAttributeMaxDynamicSharedMemorySize, SMEM_BYTES);

    init_kernel<<<1, 32>>>();
    gate_kernel<<<T_TOK, 256>>>(x, gw);
    offs_kernel<<<1, 32>>>();
    scatter_kernel<<<(T_TOK + 255) / 256, 256>>>();

    {
        int n4 = T_TOK * H_DIM / 4;
        split_kernel<0><<<(n4 + 255) / 256, 256>>>(x, n4);
        n4 = E_NUM * N1 * H_DIM / 4;
        split_kernel<1><<<(n4 + 255) / 256, 256>>>(w1, n4);
        n4 = E_NUM * H_DIM * I_DIM / 4;
        split_kernel<2><<<(n4 + 255) / 256, 256>>>(w2, n4);
    }

    dim3 grid1(N1 / 256, T_TOK / 128, E_NUM);    // 11 x 16 x 8
    moe_gemm<H_DIM/32, H_DIM, N1, N1, true><<<grid1, 256, SMEM_BYTES>>>();

    int actth = NPAIR * (I_DIM / 4);
    act_kernel<<<(actth + 255) / 256, 256>>>();

    dim3 grid2(H_DIM / 256, T_TOK / 128, E_NUM); // 8 x 16 x 8
    moe_gemm<I_DIM/32, I_DIM, H_DIM, H_DIM, false><<<grid2, 256, SMEM_BYTES>>>();

    combine_kernel<<<(T_TOK * (H_DIM / 4) + 255) / 256, 256>>>(out);
}